// round 15
// baseline (speedup 1.0000x reference)
#include <cuda_runtime.h>
#include <cstdint>

// Problem constants
#define FEAT   2104
#define TOK    1024
#define BB     8
#define NN     128
#define SS     50
#define GROUPS (BB*NN)        // 1024 (b,n) pairs
#define MFULL  (GROUPS*SS)    // 51200 rows total

// ---------------- scratch (static __device__, no allocations) ----------------
__device__ float              g_Xp[(size_t)MFULL * FEAT];   // packed concat features (~431 MB)
__device__ float              g_Hsum[GROUPS * FEAT];        // Sum_s mask*relu(...)/50  == Hmean
__device__ int                g_cnt[GROUPS];
__device__ int                g_start[GROUPS];
__device__ float              g_scale[GROUPS];              // cnt/50 (bias2 scale)
__device__ unsigned long long g_bits[GROUPS];               // 50 mask bits per group
__device__ int                g_rowsrc[MFULL];              // packed row -> original row (bn*50+s)
__device__ int                g_rowbn[MFULL];               // packed row -> bn
__device__ int                g_Mc;                         // total packed rows
__device__ int                g_layout;                     // 0=int32, 1=byte, 2=float32

// ---------------- mask dtype detection ----------------
// bool may arrive serialized as int32 {0,1}, uint8 {0,1}, or float32 {0,1.0f}.
// Sample 1024 words (4096 bytes; safe under every layout since the smallest
// possible buffer is 51200 bytes) and classify by byte pattern.
__global__ void detect_kernel(const unsigned int* __restrict__ m) {
    __shared__ int s_not01, s_notf, s_anyf;
    if (threadIdx.x == 0) { s_not01 = 0; s_notf = 0; s_anyf = 0; }
    __syncthreads();
    for (int i = threadIdx.x; i < 1024; i += blockDim.x) {
        unsigned int w = m[i];
        if (!(w == 0u || w == 1u))           atomicOr(&s_not01, 1);
        if (!(w == 0u || w == 0x3F800000u))  atomicOr(&s_notf, 1);
        if (w == 0x3F800000u)                atomicOr(&s_anyf, 1);
    }
    __syncthreads();
    if (threadIdx.x == 0) {
        int L;
        if (!s_notf && s_anyf) L = 2;   // float32 pattern
        else if (!s_not01)     L = 0;   // int32 pattern
        else                   L = 1;   // packed bytes
        g_layout = L;
    }
}

__device__ __forceinline__ int mask_bit(const void* m, int idx, int L) {
    if (L == 0) return ((const int*)m)[idx] != 0;
    if (L == 1) return ((const unsigned char*)m)[idx] != 0;
    return ((const float*)m)[idx] != 0.0f;
}

// One warp per (b,n) group: build 50-bit mask word + count.
__global__ void decode_kernel(const void* __restrict__ m) {
    int warp = (blockIdx.x * blockDim.x + threadIdx.x) >> 5;
    int lane = threadIdx.x & 31;
    if (warp >= GROUPS) return;
    int L = g_layout;
    int base = warp * SS;
    int b0 = mask_bit(m, base + lane, L);                            // s = 0..31
    int b1 = (lane < SS - 32) ? mask_bit(m, base + 32 + lane, L) : 0; // s = 32..49
    unsigned lo = __ballot_sync(0xFFFFFFFFu, b0);
    unsigned hi = __ballot_sync(0xFFFFFFFFu, b1);
    if (lane == 0) {
        int cnt = __popc(lo) + __popc(hi);
        g_cnt[warp]   = cnt;
        g_scale[warp] = cnt * (1.0f / SS);
        g_bits[warp]  = ((unsigned long long)hi << 32) | lo;
    }
}

// Exclusive prefix over 1024 group counts -> row offsets + total Mc.
__global__ void scan_kernel() {
    __shared__ int sh[GROUPS];
    int t = threadIdx.x;
    sh[t] = g_cnt[t];
    __syncthreads();
    for (int off = 1; off < GROUPS; off <<= 1) {
        int v = (t >= off) ? sh[t - off] : 0;
        __syncthreads();
        sh[t] += v;
        __syncthreads();
    }
    g_start[t] = sh[t] - g_cnt[t];
    if (t == GROUPS - 1) g_Mc = sh[t];
}

// One warp per group: write packed-row -> source-row maps.
__global__ void fillmap_kernel() {
    int warp = (blockIdx.x * blockDim.x + threadIdx.x) >> 5;
    int lane = threadIdx.x & 31;
    if (warp >= GROUPS) return;
    unsigned long long bits = g_bits[warp];
    unsigned lo = (unsigned)bits, hi = (unsigned)(bits >> 32);
    int start = g_start[warp];
    if ((lo >> lane) & 1u) {
        int j = __popc(lo & ((1u << lane) - 1u));
        g_rowsrc[start + j] = warp * SS + lane;
        g_rowbn [start + j] = warp;
    }
    if (lane < SS - 32 && ((hi >> lane) & 1u)) {
        int j = __popc(lo) + __popc(hi & ((1u << lane) - 1u));
        g_rowsrc[start + j] = warp * SS + 32 + lane;
        g_rowbn [start + j] = warp;
    }
}

__global__ void zero_hsum_kernel() {
    int n = GROUPS * FEAT;
    for (int i = blockIdx.x * blockDim.x + threadIdx.x; i < n; i += gridDim.x * blockDim.x)
        g_Hsum[i] = 0.0f;
}

// Gather concat features for each packed (unmasked) row.
__global__ void pack_kernel(const float* __restrict__ emb, const float* __restrict__ vis,
                            const float* __restrict__ bbox, const float* __restrict__ kp) {
    int r = blockIdx.x;
    if (r >= g_Mc) return;
    int src = g_rowsrc[r];
    float* dst = g_Xp + (size_t)r * FEAT;
    const float* e = emb + (size_t)src * 2048;
    for (int f = threadIdx.x; f < 2048; f += blockDim.x) dst[f] = e[f];
    int t = threadIdx.x;
    if (t < 56) {
        float v;
        if (t == 0)      v = vis[src];
        else if (t < 5)  v = bbox[src * 4 + (t - 1)];
        else             v = kp[src * 51 + (t - 5)];
        dst[2048 + t] = v;
    }
}

// ---------------- packed-f32x2 SGEMM ----------------
__device__ __forceinline__ unsigned long long pack_dup(float x) {
    unsigned long long r;
    asm("mov.b64 %0, {%1, %1};" : "=l"(r) : "f"(x));
    return r;
}
__device__ __forceinline__ void fma2(unsigned long long& d, unsigned long long a, unsigned long long b) {
    asm("fma.rn.f32x2 %0, %1, %2, %0;" : "+l"(d) : "l"(a), "l"(b));
}
__device__ __forceinline__ float2 unpack2(unsigned long long v) {
    float2 f;
    asm("mov.b64 {%0, %1}, %2;" : "=f"(f.x), "=f"(f.y) : "l"(v));
    return f;
}

// MODE 0: C = relu(Xp @ W1 + b1)/50, scatter-add into g_Hsum by (b,n) group.
// MODE 1: out = g_Hsum @ W2 + b2 * scale[row].
template<int BM, int BN, int BK, int TM, int TN, int MODE>
__global__ void __launch_bounds__(256)
gemm_kernel(const float* __restrict__ Bmat, const float* __restrict__ bias,
            float* __restrict__ Cout, int M, int K, int N, int ldb)
{
    const float* A;
    int Meff;
    if constexpr (MODE == 0) { A = g_Xp;   Meff = g_Mc; }
    else                     { A = g_Hsum; Meff = M;   }
    const int lda = FEAT;

    int m0 = blockIdx.y * BM;
    int n0 = blockIdx.x * BN;
    if (m0 >= Meff) return;

    __shared__ float As[BK][BM + 4];
    __shared__ __align__(16) float Bs[BK][BN];

    int tid = threadIdx.x;
    constexpr int A4 = BK / 4;
    int aRow = tid / A4;
    int aK   = (tid % A4) * 4;
    constexpr int B4 = BN / 4;
    int bK = tid / B4;
    int bN = (tid % B4) * 4;

    constexpr int TX = BN / TN;
    int tx = tid % TX;
    int ty = tid / TX;

    unsigned long long acc[TM][TN / 2] = {};

    int nK = (K + BK - 1) / BK;
    for (int kt = 0; kt < nK; kt++) {
        int k0 = kt * BK;

        float4 va = make_float4(0.f, 0.f, 0.f, 0.f);
        int gr = m0 + aRow, gk = k0 + aK;
        if (gr < Meff && gk < K)
            va = *reinterpret_cast<const float4*>(A + (size_t)gr * lda + gk);
        As[aK + 0][aRow] = va.x; As[aK + 1][aRow] = va.y;
        As[aK + 2][aRow] = va.z; As[aK + 3][aRow] = va.w;

        float4 vb = make_float4(0.f, 0.f, 0.f, 0.f);
        int gkb = k0 + bK, gn = n0 + bN;
        if (gkb < K && gn < N)
            vb = *reinterpret_cast<const float4*>(Bmat + (size_t)gkb * ldb + gn);
        *reinterpret_cast<float4*>(&Bs[bK][bN]) = vb;

        __syncthreads();

        #pragma unroll
        for (int k = 0; k < BK; k++) {
            unsigned long long rb[TN / 2];
            const unsigned long long* bp =
                reinterpret_cast<const unsigned long long*>(&Bs[k][tx * TN]);
            #pragma unroll
            for (int j = 0; j < TN / 2; j++) rb[j] = bp[j];
            #pragma unroll
            for (int i = 0; i < TM; i++) {
                unsigned long long ra = pack_dup(As[k][ty * TM + i]);
                #pragma unroll
                for (int j = 0; j < TN / 2; j++) fma2(acc[i][j], ra, rb[j]);
            }
        }
        __syncthreads();
    }

    if constexpr (MODE == 0) {
        #pragma unroll
        for (int i = 0; i < TM; i++) {
            int r = m0 + ty * TM + i;
            if (r >= Meff) continue;
            int bn = g_rowbn[r];
            float* hrow = g_Hsum + (size_t)bn * FEAT;
            #pragma unroll
            for (int j = 0; j < TN / 2; j++) {
                float2 v = unpack2(acc[i][j]);
                int c0 = n0 + tx * TN + 2 * j;
                if (c0 < N) {
                    float vx = v.x + bias[c0];
                    if (vx > 0.f) atomicAdd(&hrow[c0], vx * (1.0f / SS));
                }
                if (c0 + 1 < N) {
                    float vy = v.y + bias[c0 + 1];
                    if (vy > 0.f) atomicAdd(&hrow[c0 + 1], vy * (1.0f / SS));
                }
            }
        }
    } else {
        #pragma unroll
        for (int i = 0; i < TM; i++) {
            int r = m0 + ty * TM + i;
            if (r >= Meff) continue;
            float sc = g_scale[r];
            #pragma unroll
            for (int j = 0; j < TN / 2; j++) {
                float2 v = unpack2(acc[i][j]);
                int c0 = n0 + tx * TN + 2 * j;
                if (c0 < N)     Cout[(size_t)r * N + c0]     = v.x + bias[c0] * sc;
                if (c0 + 1 < N) Cout[(size_t)r * N + c0 + 1] = v.y + bias[c0 + 1] * sc;
            }
        }
    }
}

// ---------------- launch ----------------
extern "C" void kernel_launch(void* const* d_in, const int* in_sizes, int n_in,
                              void* d_out, int out_size) {
    (void)in_sizes; (void)n_in; (void)out_size;
    const float* emb  = (const float*)d_in[0];
    const float* vis  = (const float*)d_in[1];
    const float* bbox = (const float*)d_in[2];
    const float* kp   = (const float*)d_in[3];
    const void*  msk  = d_in[4];
    const float* W1   = (const float*)d_in[5];
    const float* b1   = (const float*)d_in[6];
    const float* W2   = (const float*)d_in[7];
    const float* b2   = (const float*)d_in[8];
    float* out = (float*)d_out;

    detect_kernel <<<1, 256>>>((const unsigned int*)msk);
    decode_kernel <<<GROUPS / 8, 256>>>(msk);
    scan_kernel   <<<1, GROUPS>>>();
    fillmap_kernel<<<GROUPS / 8, 256>>>();
    zero_hsum_kernel<<<2048, 256>>>();
    pack_kernel   <<<MFULL, 256>>>(emb, vis, bbox, kp);

    // GEMM1: [Mc x 2104] @ [2104 x 2104], relu+bias, masked-mean scatter
    gemm_kernel<128, 128, 8, 8, 8, 0>
        <<<dim3((FEAT + 127) / 128, (MFULL + 127) / 128), 256>>>(
            W1, b1, nullptr, MFULL, FEAT, FEAT, FEAT);

    // GEMM2: [1024 x 2104] @ [2104 x 1024] + b2*cnt/50 -> out
    gemm_kernel<64, 64, 16, 4, 4, 1>
        <<<dim3(TOK / 64, GROUPS / 64), 256>>>(
            W2, b2, out, GROUPS, FEAT, TOK, TOK);
}